// round 11
// baseline (speedup 1.0000x reference)
#include <cuda_runtime.h>
#include <cuda_fp16.h>
#include <math.h>
#include <stdint.h>

// ---------------- problem constants ----------------
constexpr int B_   = 32768;
constexpr int ZD   = 64;
constexpr int XD   = 256;
constexpr int HID  = 512;
constexpr int T_   = 8;
constexpr int NB   = 8;
constexpr int MULT = 23;        // 3*NB-1
constexpr int O3   = 1472;      // ZD*MULT
constexpr int O3Q  = 1536;      // 64 d * 24 (per-d padded layout)
constexpr int KCAT = 320;       // ZD + XD
constexpr int NDT  = 16;        // lad partial slots (8 merged tiles x 2 halves)
#define TAILF 25.0f

// merged GEMM3 tiles: tile jm covers d in [8jm, 8jm+8); K = ceil(cnt(hdeg<=8jm+7)/64)*64
__constant__ int c_k3m[8] = {64, 128, 192, 256, 320, 384, 448, 512};

// ---------------- device scratch (static, allocation-free) ----------------
__device__ __align__(16) __half g_W2m[T_ * HID * HID];           // masked W2, sorted both dims
__device__ __align__(16) __half g_WcT[T_ * XD * HID];            // Wc^T, cols sorted
__device__ __align__(16) __half g_Wxz[T_ * HID * XD];            // W2m @ Wc   [512][256]
__device__ __align__(16) __half g_Wz [T_ * HID * ZD];            // W2m @ W1m  [512][64]
__device__ __align__(16) float  g_bias2[T_ * HID];               // W2m@(b1+bc) + b2
__device__ __align__(16) __half g_W3m[(size_t)T_ * O3Q * HID];   // per-d padded rows
__device__ __align__(16) float  g_b3p[T_ * O3Q];
__device__ __align__(16) __half g_Acat[(size_t)B_ * KCAT];       // [0,64)=cur, [64,320)=x
__device__ __align__(16) __half g_Hx2[(size_t)T_ * B_ * HID];    // x-path through layers 1+2
__device__ __align__(16) __half g_h2[(size_t)B_ * HID];
__device__ float g_ladp[NDT * B_];

__device__ __forceinline__ int hdeg(int j) { return j % (ZD - 1) + 1; } // 1..63
// sorted-position -> original hidden index (stable sort by degree)
__device__ __forceinline__ int origrow(int r) {
    return (r < 72) ? (r / 9) + 63 * (r % 9)
                    : (8 + (r - 72) / 8) + 63 * ((r - 72) % 8);
}
// degree of sorted position j
__device__ __forceinline__ int degsorted(int j) {
    return (j < 72) ? (j / 9) + 1 : 9 + ((j - 72) >> 3);
}
// count of sorted positions with degree <= hv
__device__ __forceinline__ int cntdeg(int hv) {
    return (hv <= 8) ? 9 * hv : 72 + (hv - 8) * 8;
}

// ---------------- PTX helpers ----------------
__device__ __forceinline__ uint32_t smem_u32(const void* p) {
    uint32_t a;
    asm("{ .reg .u64 t; cvta.to.shared.u64 t, %1; cvt.u32.u64 %0, t; }" : "=r"(a) : "l"(p));
    return a;
}
__device__ __forceinline__ void cpasync16(uint32_t s, const void* g) {
    asm volatile("cp.async.cg.shared.global [%0], [%1], 16;" :: "r"(s), "l"(g));
}
__device__ __forceinline__ void cp_commit() {
    asm volatile("cp.async.commit_group;" ::: "memory");
}
template <int N>
__device__ __forceinline__ void cp_wait() {
    asm volatile("cp.async.wait_group %0;" :: "n"(N) : "memory");
}
__device__ __forceinline__ void ldsm4(uint32_t* r, uint32_t addr) {
    asm volatile("ldmatrix.sync.aligned.m8n8.x4.shared.b16 {%0,%1,%2,%3}, [%4];"
        : "=r"(r[0]), "=r"(r[1]), "=r"(r[2]), "=r"(r[3]) : "r"(addr));
}
__device__ __forceinline__ void mma_f16(float* c, const uint32_t* a, uint32_t b0, uint32_t b1) {
    asm volatile("mma.sync.aligned.m16n8k16.row.col.f32.f16.f16.f32 "
        "{%0,%1,%2,%3}, {%4,%5,%6,%7}, {%8,%9}, {%0,%1,%2,%3};"
        : "+f"(c[0]), "+f"(c[1]), "+f"(c[2]), "+f"(c[3])
        : "r"(a[0]), "r"(a[1]), "r"(a[2]), "r"(a[3]), "r"(b0), "r"(b1));
}

// fast exp on the FMA pipe: rel err ~2e-7, valid |x| <= 80
__device__ __forceinline__ float fexp(float x) {
    x = fminf(fmaxf(x, -80.f), 80.f);
    float t = fmaf(x, 1.4426950408889634f, 12582912.0f);
    float i = t - 12582912.0f;
    float f = fmaf(x, 1.4426950408889634f, -i);
    float p = 1.3333558146e-3f;
    p = fmaf(p, f, 9.6181291076e-3f);
    p = fmaf(p, f, 5.5504108665e-2f);
    p = fmaf(p, f, 2.4022650696e-1f);
    p = fmaf(p, f, 6.9314718056e-1f);
    p = fmaf(p, f, 1.0f);
    return __int_as_float(__float_as_int(p) + ((int)i << 23));
}
__device__ __forceinline__ float softplus_f(float x) {
    return fmaxf(x, 0.f) + log1pf(fexp(-fabsf(x)));
}

// ---------------- prep kernels ----------------
__global__ void k_prep_w2(const float* __restrict__ W2) {
    int i = blockIdx.x * blockDim.x + threadIdx.x;
    if (i >= T_ * HID * HID) return;
    int c = i % HID;
    int r = (i / HID) % HID;
    int t = i / (HID * HID);
    int orow = origrow(r), ocol = origrow(c);
    float v = (hdeg(orow) >= hdeg(ocol))
            ? W2[((size_t)t * HID + orow) * HID + ocol] : 0.f;
    g_W2m[i] = __float2half_rn(v);
}

__global__ void k_prep_wcT(const float* __restrict__ Wc) {
    int i = blockIdx.x * blockDim.x + threadIdx.x;
    if (i >= T_ * XD * HID) return;
    int j = i % HID;                  // sorted hidden
    int c = (i / HID) % XD;
    int t = i / (HID * XD);
    g_WcT[i] = __float2half_rn(Wc[((size_t)t * HID + origrow(j)) * XD + c]);
}

// Wz[t][r][d] = sum_j W2m[r,j] * W1m[j,d]  — one block per (t,r), 4 strips x 64 d
__global__ __launch_bounds__(256)
void k_prep_wz(const float* __restrict__ W1, const float* __restrict__ W2) {
    const int blk = blockIdx.x;          // 0 .. T_*HID-1
    const int r = blk % HID, t = blk / HID;
    const int orow = origrow(r);
    const int jend = cntdeg(hdeg(orow)); // W2 mask: deg(j) <= deg(r)
    const int d = threadIdx.x & 63;
    const int strip = threadIdx.x >> 6;  // 0..3
    const float* W2row = W2 + ((size_t)t * HID + orow) * HID;
    const float* W1t   = W1 + (size_t)t * HID * ZD;
    float acc = 0.f;
    for (int j = strip; j < jend; j += 4) {
        if (degsorted(j) > d) {          // W1 mask: deg(j) >= d+1
            int oj = origrow(j);
            acc += W2row[oj] * W1t[(size_t)oj * ZD + d];
        }
    }
    __shared__ float red[4][64];
    red[strip][d] = acc;
    __syncthreads();
    if (threadIdx.x < 64) {
        float v = red[0][d] + red[1][d] + red[2][d] + red[3][d];
        g_Wz[((size_t)t * HID + r) * ZD + d] = __float2half_rn(v);
    }
}

// bias2[t][r] = W2m[r,:] @ (b1+bc) + b2 — one warp per (t,r)
__global__ __launch_bounds__(256)
void k_prep_bias2(const float* __restrict__ W2, const float* __restrict__ b1,
                  const float* __restrict__ bc, const float* __restrict__ b2) {
    int w = (blockIdx.x * blockDim.x + threadIdx.x) >> 5;
    int lane = threadIdx.x & 31;
    if (w >= T_ * HID) return;
    int r = w % HID, t = w / HID;
    int orow = origrow(r);
    int jend = cntdeg(hdeg(orow));
    const float* W2row = W2 + ((size_t)t * HID + orow) * HID;
    float acc = 0.f;
    for (int j = lane; j < jend; j += 32) {
        int oj = origrow(j);
        acc += W2row[oj] * (b1[(size_t)t * HID + oj] + bc[(size_t)t * HID + oj]);
    }
#pragma unroll
    for (int off = 16; off; off >>= 1) acc += __shfl_xor_sync(0xffffffffu, acc, off);
    if (lane == 0) g_bias2[w] = acc + b2[(size_t)t * HID + orow];
}

// W3 per-d padded rows: rp = d*24 + j
__global__ void k_prep_w3(const float* __restrict__ W3, const float* __restrict__ b3) {
    size_t i = (size_t)blockIdx.x * blockDim.x + threadIdx.x;
    size_t total = (size_t)T_ * O3Q * HID;
    if (i < total) {
        int c  = (int)(i % HID);
        int rp = (int)((i / HID) % O3Q);
        int t  = (int)(i / ((size_t)HID * O3Q));
        int d = rp / 24, j = rp % 24;
        float v = 0.f;
        if (j < 23) {
            int ocol = origrow(c);
            if (d + 1 > hdeg(ocol)) v = W3[((size_t)t * O3 + d * 23 + j) * HID + ocol];
        }
        g_W3m[i] = __float2half_rn(v);
    }
    if (i < (size_t)(T_ * O3Q)) {
        int rp = (int)(i % O3Q), t = (int)(i / O3Q);
        int d = rp / 24, j = rp % 24;
        g_b3p[i] = (j < 23) ? b3[(size_t)t * O3 + d * 23 + j] : 0.f;
    }
}

__global__ void k_init(const float* __restrict__ z, const float* __restrict__ x) {
    int i = blockIdx.x * blockDim.x + threadIdx.x;
    if (i < B_ * XD) {
        int b = i / XD, j = i % XD;
        g_Acat[(size_t)b * KCAT + ZD + j] = __float2half_rn(x[i]);
    }
    if (i < B_ * ZD) {
        int b = i / ZD, d = i % ZD;
        g_Acat[(size_t)b * KCAT + d] = __float2half_rn(z[i]);
    }
    if (i < NDT * B_) g_ladp[i] = 0.f;
}

// ---------------- generic fp16 NT GEMM: C = A@W^T (+bias)(+aux)(relu) ----------------
constexpr int STAGE_BYTES = 32768;
constexpr int SMEM_BYTES  = 3 * STAGE_BYTES + 1024;

template <bool RELU, bool BIAS, bool AUX>
__global__ __launch_bounds__(128, 2)
void k_hg(const __half* __restrict__ A, int ldA, size_t zA,
          const __half* __restrict__ W, size_t zW,
          const float* __restrict__ bias, size_t zB,
          const __half* __restrict__ aux, size_t zX,
          __half* __restrict__ C, size_t zC,
          int K) {
    extern __shared__ char smraw[];
    const uint32_t base = (smem_u32(smraw) + 1023u) & ~1023u;

    const size_t zz = blockIdx.z;
    A += zz * zA;  W += zz * zW;  C += zz * zC;
    if (BIAS) bias += zz * zB;
    if (AUX)  aux  += zz * zX;

    const int tid  = threadIdx.x;
    const int warp = tid >> 5;
    const int lane = tid & 31;
    const int KC = K >> 6;

    const int trow = tid >> 3;
    const int c4   = tid & 7;
    const uint32_t sfix = (uint32_t)((c4 ^ (trow & 7)) * 16);
    const size_t KbA = (size_t)ldA * 2;
    const size_t KbW = (size_t)K * 2;
    const char* Ag = (const char*)A + (size_t)(blockIdx.y * 128 + trow) * KbA + c4 * 16;
    const char* Wg = (const char*)W + (size_t)(blockIdx.x * 128 + trow) * KbW + c4 * 16;

    auto issue = [&](int chunk) {
        const uint32_t stA = base + (uint32_t)(chunk % 3) * STAGE_BYTES;
        const uint32_t stB = stA + 16384;
        const size_t go = (size_t)chunk * 128;
#pragma unroll
        for (int i = 0; i < 8; i++) {
            uint32_t so = (uint32_t)(trow + 16 * i) * 128u + sfix;
            cpasync16(stA + so, Ag + (size_t)(16 * i) * KbA + go);
            cpasync16(stB + so, Wg + (size_t)(16 * i) * KbW + go);
        }
    };

    issue(0); cp_commit();
    if (KC > 1) issue(1);
    cp_commit();

    const int wm = (warp & 1) * 64;
    const int wn = (warp >> 1) * 64;
    const int lrow = lane & 15;
    const int lkh  = lane >> 4;

    float acc[4][8][4];
#pragma unroll
    for (int mf = 0; mf < 4; mf++)
#pragma unroll
        for (int nf = 0; nf < 8; nf++)
#pragma unroll
            for (int e = 0; e < 4; e++) acc[mf][nf][e] = 0.f;

    for (int i = 0; i < KC; i++) {
        cp_wait<1>();
        __syncthreads();
        if (i + 2 < KC) issue(i + 2);
        cp_commit();

        const uint32_t stA = base + (uint32_t)(i % 3) * STAGE_BYTES;
        const uint32_t stB = stA + 16384;
#pragma unroll
        for (int ks = 0; ks < 4; ks++) {
            uint32_t a[4][4], b[4][4];
#pragma unroll
            for (int mf = 0; mf < 4; mf++) {
                int row = wm + mf * 16 + lrow;
                uint32_t seg = (uint32_t)((2 * ks + lkh) ^ (row & 7));
                ldsm4(a[mf], stA + (uint32_t)row * 128u + seg * 16u);
            }
#pragma unroll
            for (int p = 0; p < 4; p++) {
                int row = wn + p * 16 + lrow;
                uint32_t seg = (uint32_t)((2 * ks + lkh) ^ (row & 7));
                ldsm4(b[p], stB + (uint32_t)row * 128u + seg * 16u);
            }
#pragma unroll
            for (int mf = 0; mf < 4; mf++)
#pragma unroll
                for (int p = 0; p < 4; p++) {
                    mma_f16(acc[mf][2 * p],     a[mf], b[p][0], b[p][2]);
                    mma_f16(acc[mf][2 * p + 1], a[mf], b[p][1], b[p][3]);
                }
        }
    }

    const int N = gridDim.x * 128;
    const int gm0 = blockIdx.y * 128 + wm + (lane >> 2);
    const int gn0 = blockIdx.x * 128 + wn + (lane & 3) * 2;
#pragma unroll
    for (int nf = 0; nf < 8; nf++) {
        const int cc = gn0 + nf * 8;
        float bv0 = 0.f, bv1 = 0.f;
        if (BIAS) { bv0 = bias[cc]; bv1 = bias[cc + 1]; }
#pragma unroll
        for (int mf = 0; mf < 4; mf++) {
            const size_t r0 = (size_t)(gm0 + mf * 16);
            float v0 = acc[mf][nf][0] + bv0;
            float v1 = acc[mf][nf][1] + bv1;
            float v2 = acc[mf][nf][2] + bv0;
            float v3 = acc[mf][nf][3] + bv1;
            if (AUX) {
                float2 x0 = __half22float2(*(const __half2*)(aux + r0 * N + cc));
                float2 x1 = __half22float2(*(const __half2*)(aux + (r0 + 8) * N + cc));
                v0 += x0.x; v1 += x0.y; v2 += x1.x; v3 += x1.y;
            }
            if (RELU) {
                v0 = fmaxf(v0, 0.f); v1 = fmaxf(v1, 0.f);
                v2 = fmaxf(v2, 0.f); v3 = fmaxf(v3, 0.f);
            }
            *(__half2*)(C + r0 * N + cc)       = __floats2half2_rn(v0, v1);
            *(__half2*)(C + (r0 + 8) * N + cc) = __floats2half2_rn(v2, v3);
        }
    }
}

// ---------------- fused GEMM3 + RQ-spline (merged tile 128x192 = 8 d's) ----------------
// 256 threads, 8 warps as 2(M) x 4(N), warp tile 64x48.
constexpr int G3_STAGE = 40960;                 // 16KB A + 24KB B
constexpr int G3_SMEM  = 3 * G3_STAGE + 1024;   // epilogue buffer 128*193*4 = 98.8KB fits
constexpr int ESTR = 193;                       // epilogue row stride (floats, odd)

__global__ __launch_bounds__(256, 1)
void k_g3spline(const __half* __restrict__ A, const __half* __restrict__ W,
                const float* __restrict__ bias) {
    extern __shared__ char smraw[];
    const uint32_t base = (smem_u32(smraw) + 1023u) & ~1023u;
    const uint32_t pad  = base - smem_u32(smraw);
    float* sp = (float*)(smraw + pad);

    const int tid  = threadIdx.x;
    const int warp = tid >> 5;
    const int lane = tid & 31;
    const int K = HID;

    const int dt = 7 - blockIdx.x;          // heavy-K tiles launch first
    const int Krun = c_k3m[dt];
    const int KC = Krun >> 6;

    const int trow = tid >> 3;              // 0..31
    const int c4   = tid & 7;
    const uint32_t sfix = (uint32_t)((c4 ^ (trow & 7)) * 16);
    const size_t Kb = (size_t)K * 2;
    const char* Ag = (const char*)A + (size_t)(blockIdx.y * 128 + trow) * Kb + c4 * 16;
    const char* Wg = (const char*)W + (size_t)(dt * 192 + trow) * Kb + c4 * 16;

    auto issue = [&](int chunk) {
        const uint32_t stA = base + (uint32_t)(chunk % 3) * G3_STAGE;
        const uint32_t stB = stA + 16384;
        const size_t go = (size_t)chunk * 128;
#pragma unroll
        for (int i = 0; i < 4; i++) {       // A: 128 rows
            uint32_t so = (uint32_t)(trow + 32 * i) * 128u + sfix;
            cpasync16(stA + so, Ag + (size_t)(32 * i) * Kb + go);
        }
#pragma unroll
        for (int i = 0; i < 6; i++) {       // B: 192 rows
            uint32_t so = (uint32_t)(trow + 32 * i) * 128u + sfix;
            cpasync16(stB + so, Wg + (size_t)(32 * i) * Kb + go);
        }
    };

    issue(0); cp_commit();
    if (KC > 1) issue(1);
    cp_commit();

    const int wm  = (warp & 1) * 64;
    const int wnl = (warp >> 1) * 48;       // 0,48,96,144
    const int lrow = lane & 15;
    const int lkh  = lane >> 4;

    float acc[4][6][4];
#pragma unroll
    for (int mf = 0; mf < 4; mf++)
#pragma unroll
        for (int nf = 0; nf < 6; nf++)
#pragma unroll
            for (int e = 0; e < 4; e++) acc[mf][nf][e] = 0.f;

    for (int i = 0; i < KC; i++) {
        cp_wait<1>();
        __syncthreads();
        if (i + 2 < KC) issue(i + 2);
        cp_commit();

        const uint32_t stA = base + (uint32_t)(i % 3) * G3_STAGE;
        const uint32_t stB = stA + 16384;
#pragma unroll
        for (int ks = 0; ks < 4; ks++) {
            uint32_t a[4][4], b[3][4];
#pragma unroll
            for (int mf = 0; mf < 4; mf++) {
                int row = wm + mf * 16 + lrow;
                uint32_t seg = (uint32_t)((2 * ks + lkh) ^ (row & 7));
                ldsm4(a[mf], stA + (uint32_t)row * 128u + seg * 16u);
            }
#pragma unroll
            for (int p = 0; p < 3; p++) {
                int row = wnl + p * 16 + lrow;
                uint32_t seg = (uint32_t)((2 * ks + lkh) ^ (row & 7));
                ldsm4(b[p], stB + (uint32_t)row * 128u + seg * 16u);
            }
#pragma unroll
            for (int mf = 0; mf < 4; mf++)
#pragma unroll
                for (int p = 0; p < 3; p++) {
                    mma_f16(acc[mf][2 * p],     a[mf], b[p][0], b[p][2]);
                    mma_f16(acc[mf][2 * p + 1], a[mf], b[p][1], b[p][3]);
                }
        }
    }

    cp_wait<0>();
    __syncthreads();

    // acc + bias -> smem [row][col], stride ESTR floats
    {
        const int r0 = wm + (lane >> 2);
        const int c0 = wnl + (lane & 3) * 2;
        const int gb = dt * 192;
#pragma unroll
        for (int nf = 0; nf < 6; nf++) {
            const int cc = c0 + nf * 8;
            const float bv0 = bias[gb + cc];
            const float bv1 = bias[gb + cc + 1];
#pragma unroll
            for (int mf = 0; mf < 4; mf++) {
                const int rr = r0 + mf * 16;
                sp[rr * ESTR + cc]           = acc[mf][nf][0] + bv0;
                sp[rr * ESTR + cc + 1]       = acc[mf][nf][1] + bv1;
                sp[(rr + 8) * ESTR + cc]     = acc[mf][nf][2] + bv0;
                sp[(rr + 8) * ESTR + cc + 1] = acc[mf][nf][3] + bv1;
            }
        }
    }
    __syncthreads();

    // spline: thread group g = tid>>7 handles d-local [4g,4g+4) for row tid&127
    const int g = tid >> 7;
    const int row = tid & 127;
    const int bglob = blockIdx.y * 128 + row;
    const float ISH = 0.04419417382415922f;  // 1/sqrt(512)
    float ladsum = 0.f;
#pragma unroll 1
    for (int dl = 0; dl < 4; dl++) {
        const int dloc = g * 4 + dl;
        const int d = dt * 8 + dloc;
        const float* pp = sp + row * ESTR + dloc * 24;
        float z = __half2float(g_Acat[(size_t)bglob * KCAT + d]);

        float cumw[NB + 1], cumh[NB + 1];
        {
            float mx = pp[0];
#pragma unroll
            for (int i = 1; i < NB; i++) mx = fmaxf(mx, pp[i]);
            float e[NB], s = 0.f;
#pragma unroll
            for (int i = 0; i < NB; i++) { e[i] = fexp((pp[i] - mx) * ISH); s += e[i]; }
            float inv = __fdividef(1.f, s);
            const float fac = 1.f - NB * 0.001f;
            cumw[0] = -TAILF;
            float run = 0.f;
#pragma unroll
            for (int i = 0; i < NB; i++) {
                run += 0.001f + fac * e[i] * inv;
                cumw[i + 1] = -TAILF + 2.f * TAILF * run;
            }
            cumw[NB] = TAILF;
        }
        {
            float mx = pp[NB];
#pragma unroll
            for (int i = 1; i < NB; i++) mx = fmaxf(mx, pp[NB + i]);
            float e[NB], s = 0.f;
#pragma unroll
            for (int i = 0; i < NB; i++) { e[i] = fexp((pp[NB + i] - mx) * ISH); s += e[i]; }
            float inv = __fdividef(1.f, s);
            const float fac = 1.f - NB * 0.001f;
            cumh[0] = -TAILF;
            float run = 0.f;
#pragma unroll
            for (int i = 0; i < NB; i++) {
                run += 0.001f + fac * e[i] * inv;
                cumh[i + 1] = -TAILF + 2.f * TAILF * run;
            }
            cumh[NB] = TAILF;
        }

        float dv[NB + 1];
        dv[0] = 1.f; dv[NB] = 1.f;
#pragma unroll
        for (int k = 1; k < NB; k++) dv[k] = 0.001f + softplus_f(pp[2 * NB + k - 1]);

        float zin = fminf(fmaxf(z, -TAILF), TAILF);
        int idx = 0;
#pragma unroll
        for (int i = 1; i <= NB; i++) {
            float edge = cumw[i] + (i == NB ? 1e-6f : 0.f);
            idx += (zin >= edge) ? 1 : 0;
        }
        if (idx > NB - 1) idx = NB - 1;

        float in_cw = 0.f, in_w = 1.f, in_ch = 0.f, in_h = 1.f, d0 = 1.f, d1 = 1.f;
#pragma unroll
        for (int i = 0; i < NB; i++) {
            if (idx == i) {
                in_cw = cumw[i]; in_w = cumw[i + 1] - cumw[i];
                in_ch = cumh[i]; in_h = cumh[i + 1] - cumh[i];
                d0 = dv[i]; d1 = dv[i + 1];
            }
        }

        float rw = __fdividef(1.f, in_w);
        float delta = in_h * rw;
        float th  = (zin - in_cw) * rw;
        float th1 = th * (1.f - th);
        float num = in_h * (delta * th * th + d0 * th1);
        float den = delta + (d0 + d1 - 2.f * delta) * th1;
        float outv = in_ch + __fdividef(num, den);
        float omt = 1.f - th;
        float dnum = delta * delta * (d1 * th * th + 2.f * delta * th1 + d0 * omt * omt);
        float lad = __logf(dnum) - 2.f * __logf(den);

        bool inside = (z >= -TAILF) && (z <= TAILF);
        float newz = inside ? outv : z;
        ladsum += inside ? lad : 0.f;
        g_Acat[(size_t)bglob * KCAT + d] = __float2half_rn(newz);
    }
    // slot = dt*2 + g : unique writer per (slot, bglob) per step
    g_ladp[(dt * 2 + g) * B_ + bglob] += ladsum;
}

// ---------------- final log-prob ----------------
__global__ void k_final(float* __restrict__ out) {
    int warp = threadIdx.x >> 5;
    int b = blockIdx.x * 8 + warp;
    int lane = threadIdx.x & 31;
    float c1 = __half2float(g_Acat[(size_t)b * KCAT + lane]);
    float c2 = __half2float(g_Acat[(size_t)b * KCAT + 32 + lane]);
    float v = -0.5f * (c1 * c1 + c2 * c2);
    if (lane < NDT) v += g_ladp[lane * B_ + b];
#pragma unroll
    for (int off = 16; off; off >>= 1) v += __shfl_xor_sync(0xffffffffu, v, off);
    if (lane == 0) out[b] = v - 58.81206612510f;
}

// ---------------- launch ----------------
extern "C" void kernel_launch(void* const* d_in, const int* in_sizes, int n_in,
                              void* d_out, int out_size) {
    const float* z  = (const float*)d_in[0];
    const float* x  = (const float*)d_in[1];
    const float* W1 = (const float*)d_in[2];
    const float* b1 = (const float*)d_in[3];
    const float* Wc = (const float*)d_in[4];
    const float* bc = (const float*)d_in[5];
    const float* W2 = (const float*)d_in[6];
    const float* b2 = (const float*)d_in[7];
    const float* W3 = (const float*)d_in[8];
    const float* b3 = (const float*)d_in[9];
    float* out = (float*)d_out;

    void *pW2m, *pWcT, *pWxz, *pWz, *pBias2, *pW3m, *pB3p, *pAcat, *pHx2, *pH2;
    cudaGetSymbolAddress(&pW2m,   g_W2m);
    cudaGetSymbolAddress(&pWcT,   g_WcT);
    cudaGetSymbolAddress(&pWxz,   g_Wxz);
    cudaGetSymbolAddress(&pWz,    g_Wz);
    cudaGetSymbolAddress(&pBias2, g_bias2);
    cudaGetSymbolAddress(&pW3m,   g_W3m);
    cudaGetSymbolAddress(&pB3p,   g_b3p);
    cudaGetSymbolAddress(&pAcat,  g_Acat);
    cudaGetSymbolAddress(&pHx2,   g_Hx2);
    cudaGetSymbolAddress(&pH2,    g_h2);

    const __half* W2m  = (const __half*)pW2m;
    const __half* WcT  = (const __half*)pWcT;
    __half*       Wxz  = (__half*)pWxz;
    const __half* Wz   = (const __half*)pWz;
    const float*  Bias2= (const float*)pBias2;
    const __half* W3m  = (const __half*)pW3m;
    const float*  B3p  = (const float*)pB3p;
    const __half* Acat = (const __half*)pAcat;
    __half*       Hx2  = (__half*)pHx2;
    __half*       H2   = (__half*)pH2;

    cudaFuncSetAttribute(k_hg<false, false, false>, cudaFuncAttributeMaxDynamicSharedMemorySize, SMEM_BYTES);
    cudaFuncSetAttribute(k_hg<false, true,  false>, cudaFuncAttributeMaxDynamicSharedMemorySize, SMEM_BYTES);
    cudaFuncSetAttribute(k_hg<true,  false, true>,  cudaFuncAttributeMaxDynamicSharedMemorySize, SMEM_BYTES);
    cudaFuncSetAttribute(k_g3spline, cudaFuncAttributeMaxDynamicSharedMemorySize, G3_SMEM);

    // ---- prep (parallelized) ----
    k_prep_w2<<<(T_ * HID * HID + 255) / 256, 256>>>(W2);
    k_prep_wcT<<<(T_ * XD * HID + 255) / 256, 256>>>(Wc);
    k_prep_wz<<<T_ * HID, 256>>>(W1, W2);
    k_prep_bias2<<<(T_ * HID * 32 + 255) / 256, 256>>>(W2, b1, bc, b2);
    {
        size_t tot = (size_t)T_ * O3Q * HID;
        k_prep_w3<<<(int)((tot + 255) / 256), 256>>>(W3, b3);
    }
    k_init<<<(B_ * XD + 255) / 256, 256>>>(z, x);

    // Wxz = W2m @ WcT^T  : M=512, N=256, K=512, batched over t
    {
        dim3 g(2, 4, 8);
        k_hg<false, false, false><<<g, 128, SMEM_BYTES>>>(
            W2m, HID, (size_t)HID * HID,
            WcT, (size_t)XD * HID,
            nullptr, 0, nullptr, 0,
            Wxz, (size_t)HID * XD, HID);
    }
    // Hx2 = x @ Wxz^T + bias2 : M=B, N=512, K=256, batched over t
    {
        dim3 g(4, 256, 8);
        k_hg<false, true, false><<<g, 128, SMEM_BYTES>>>(
            Acat + ZD, KCAT, 0,
            Wxz, (size_t)HID * XD,
            Bias2, HID, nullptr, 0,
            Hx2, (size_t)B_ * HID, XD);
    }

    dim3 g2(4, 256, 1);
    dim3 g3(8, 256);
    for (int t = 0; t < T_; t++) {
        // H2 = relu(cur @ Wz^T + Hx2_t)  : K=64
        k_hg<true, false, true><<<g2, 128, SMEM_BYTES>>>(
            Acat, KCAT, 0,
            Wz + (size_t)t * HID * ZD, 0,
            nullptr, 0,
            Hx2 + (size_t)t * B_ * HID, 0,
            H2, 0, ZD);
        k_g3spline<<<g3, 256, G3_SMEM>>>(H2, W3m + (size_t)t * O3Q * HID,
                                         B3p + (size_t)t * O3Q);
    }
    k_final<<<B_ / 8, 256>>>(out);
}

// round 16
// speedup vs baseline: 1.1410x; 1.1410x over previous
#include <cuda_runtime.h>
#include <cuda_fp16.h>
#include <math.h>
#include <stdint.h>

// ---------------- problem constants ----------------
constexpr int B_   = 32768;
constexpr int ZD   = 64;
constexpr int XD   = 256;
constexpr int HID  = 512;
constexpr int T_   = 8;
constexpr int NB   = 8;
constexpr int MULT = 23;        // 3*NB-1
constexpr int O3   = 1472;      // ZD*MULT
constexpr int O3Q  = 1536;      // 64 d * 24 (per-d padded layout) = 16 tiles * 96
constexpr int KCAT = 320;       // ZD + XD
constexpr int NDT  = 16;        // g3spline d-tiles (4 d's x 96 cols each)
#define TAILF 25.0f

// fused GEMM3: tile j covers d in [4j,4j+4); K = ceil(cntdeg(4j+3)/64)*64
__constant__ int c_k3b[NDT] = {64, 64, 128, 128, 192, 192, 256, 256,
                               320, 320, 384, 384, 448, 448, 512, 512};

// ---------------- device scratch (static, allocation-free) ----------------
__device__ __align__(16) __half g_W2m[T_ * HID * HID];           // masked W2, sorted both dims
__device__ __align__(16) __half g_WcT[T_ * XD * HID];            // Wc^T, cols sorted
__device__ __align__(16) __half g_Wxz[T_ * HID * XD];            // W2m @ Wc, dense ld=256
__device__ __align__(16) __half g_Wcat2[(size_t)T_ * HID * KCAT];// [Wz | Wxz] rows, ld=320
__device__ __align__(16) float  g_bias2[T_ * HID];               // W2m@(b1+bc) + b2
__device__ __align__(16) __half g_W3m[(size_t)T_ * O3Q * HID];   // per-d padded rows
__device__ __align__(16) float  g_b3p[T_ * O3Q];
__device__ __align__(16) __half g_Acat[(size_t)B_ * KCAT];       // [0,64)=cur, [64,320)=x
__device__ __align__(16) __half g_h2[(size_t)B_ * HID];
__device__ float g_ladp[NDT * B_];

__device__ __forceinline__ int hdeg(int j) { return j % (ZD - 1) + 1; } // 1..63
// sorted-position -> original hidden index (stable sort by degree)
__device__ __forceinline__ int origrow(int r) {
    return (r < 72) ? (r / 9) + 63 * (r % 9)
                    : (8 + (r - 72) / 8) + 63 * ((r - 72) % 8);
}
// degree of sorted position j
__device__ __forceinline__ int degsorted(int j) {
    return (j < 72) ? (j / 9) + 1 : 9 + ((j - 72) >> 3);
}
// count of sorted positions with degree <= hv
__device__ __forceinline__ int cntdeg(int hv) {
    return (hv <= 8) ? 9 * hv : 72 + (hv - 8) * 8;
}

// ---------------- PTX helpers ----------------
__device__ __forceinline__ uint32_t smem_u32(const void* p) {
    uint32_t a;
    asm("{ .reg .u64 t; cvta.to.shared.u64 t, %1; cvt.u32.u64 %0, t; }" : "=r"(a) : "l"(p));
    return a;
}
__device__ __forceinline__ void cpasync16(uint32_t s, const void* g) {
    asm volatile("cp.async.cg.shared.global [%0], [%1], 16;" :: "r"(s), "l"(g));
}
__device__ __forceinline__ void cp_commit() {
    asm volatile("cp.async.commit_group;" ::: "memory");
}
template <int N>
__device__ __forceinline__ void cp_wait() {
    asm volatile("cp.async.wait_group %0;" :: "n"(N) : "memory");
}
__device__ __forceinline__ void ldsm4(uint32_t* r, uint32_t addr) {
    asm volatile("ldmatrix.sync.aligned.m8n8.x4.shared.b16 {%0,%1,%2,%3}, [%4];"
        : "=r"(r[0]), "=r"(r[1]), "=r"(r[2]), "=r"(r[3]) : "r"(addr));
}
__device__ __forceinline__ void mma_f16(float* c, const uint32_t* a, uint32_t b0, uint32_t b1) {
    asm volatile("mma.sync.aligned.m16n8k16.row.col.f32.f16.f16.f32 "
        "{%0,%1,%2,%3}, {%4,%5,%6,%7}, {%8,%9}, {%0,%1,%2,%3};"
        : "+f"(c[0]), "+f"(c[1]), "+f"(c[2]), "+f"(c[3])
        : "r"(a[0]), "r"(a[1]), "r"(a[2]), "r"(a[3]), "r"(b0), "r"(b1));
}

// fast exp on the FMA pipe: rel err ~2e-7, valid |x| <= 80
__device__ __forceinline__ float fexp(float x) {
    x = fminf(fmaxf(x, -80.f), 80.f);
    float t = fmaf(x, 1.4426950408889634f, 12582912.0f);
    float i = t - 12582912.0f;
    float f = fmaf(x, 1.4426950408889634f, -i);
    float p = 1.3333558146e-3f;
    p = fmaf(p, f, 9.6181291076e-3f);
    p = fmaf(p, f, 5.5504108665e-2f);
    p = fmaf(p, f, 2.4022650696e-1f);
    p = fmaf(p, f, 6.9314718056e-1f);
    p = fmaf(p, f, 1.0f);
    return __int_as_float(__float_as_int(p) + ((int)i << 23));
}
__device__ __forceinline__ float softplus_f(float x) {
    return fmaxf(x, 0.f) + log1pf(fexp(-fabsf(x)));
}

// ---------------- prep kernels ----------------
__global__ void k_prep_w2(const float* __restrict__ W2) {
    int i = blockIdx.x * blockDim.x + threadIdx.x;
    if (i >= T_ * HID * HID) return;
    int c = i % HID;
    int r = (i / HID) % HID;
    int t = i / (HID * HID);
    int orow = origrow(r), ocol = origrow(c);
    float v = (hdeg(orow) >= hdeg(ocol))
            ? W2[((size_t)t * HID + orow) * HID + ocol] : 0.f;
    g_W2m[i] = __float2half_rn(v);
}

__global__ void k_prep_wcT(const float* __restrict__ Wc) {
    int i = blockIdx.x * blockDim.x + threadIdx.x;
    if (i >= T_ * XD * HID) return;
    int j = i % HID;                  // sorted hidden
    int c = (i / HID) % XD;
    int t = i / (HID * XD);
    g_WcT[i] = __float2half_rn(Wc[((size_t)t * HID + origrow(j)) * XD + c]);
}

// Wz part of Wcat2 cols [0,64): Wz[t][r][d] = sum_j W2m[r,j]*W1m[j,d]
__global__ __launch_bounds__(256)
void k_prep_wz(const float* __restrict__ W1, const float* __restrict__ W2) {
    const int blk = blockIdx.x;          // 0 .. T_*HID-1
    const int r = blk % HID, t = blk / HID;
    const int orow = origrow(r);
    const int jend = cntdeg(hdeg(orow)); // W2 mask: deg(j) <= deg(r)
    const int d = threadIdx.x & 63;
    const int strip = threadIdx.x >> 6;  // 0..3
    const float* W2row = W2 + ((size_t)t * HID + orow) * HID;
    const float* W1t   = W1 + (size_t)t * HID * ZD;
    float acc = 0.f;
    for (int j = strip; j < jend; j += 4) {
        if (degsorted(j) > d) {          // W1 mask: deg(j) >= d+1
            int oj = origrow(j);
            acc += W2row[oj] * W1t[(size_t)oj * ZD + d];
        }
    }
    __shared__ float red[4][64];
    red[strip][d] = acc;
    __syncthreads();
    if (threadIdx.x < 64) {
        float v = red[0][d] + red[1][d] + red[2][d] + red[3][d];
        g_Wcat2[((size_t)t * HID + r) * KCAT + d] = __float2half_rn(v);
    }
}

// pack dense Wxz (ld=256) into Wcat2 cols [64,320)
__global__ void k_pack(void) {
    int i = blockIdx.x * blockDim.x + threadIdx.x;
    if (i >= T_ * HID * XD) return;
    int c  = i % XD;
    int tr = i / XD;                     // t*HID + r
    g_Wcat2[(size_t)tr * KCAT + ZD + c] = g_Wxz[i];
}

// bias2[t][r] = W2m[r,:] @ (b1+bc) + b2 — one warp per (t,r)
__global__ __launch_bounds__(256)
void k_prep_bias2(const float* __restrict__ W2, const float* __restrict__ b1,
                  const float* __restrict__ bc, const float* __restrict__ b2) {
    int w = (blockIdx.x * blockDim.x + threadIdx.x) >> 5;
    int lane = threadIdx.x & 31;
    if (w >= T_ * HID) return;
    int r = w % HID, t = w / HID;
    int orow = origrow(r);
    int jend = cntdeg(hdeg(orow));
    const float* W2row = W2 + ((size_t)t * HID + orow) * HID;
    float acc = 0.f;
    for (int j = lane; j < jend; j += 32) {
        int oj = origrow(j);
        acc += W2row[oj] * (b1[(size_t)t * HID + oj] + bc[(size_t)t * HID + oj]);
    }
#pragma unroll
    for (int off = 16; off; off >>= 1) acc += __shfl_xor_sync(0xffffffffu, acc, off);
    if (lane == 0) g_bias2[w] = acc + b2[(size_t)t * HID + orow];
}

// W3 per-d padded rows: rp = d*24 + j
__global__ void k_prep_w3(const float* __restrict__ W3, const float* __restrict__ b3) {
    size_t i = (size_t)blockIdx.x * blockDim.x + threadIdx.x;
    size_t total = (size_t)T_ * O3Q * HID;
    if (i < total) {
        int c  = (int)(i % HID);
        int rp = (int)((i / HID) % O3Q);
        int t  = (int)(i / ((size_t)HID * O3Q));
        int d = rp / 24, j = rp % 24;
        float v = 0.f;
        if (j < 23) {
            int ocol = origrow(c);
            if (d + 1 > hdeg(ocol)) v = W3[((size_t)t * O3 + d * 23 + j) * HID + ocol];
        }
        g_W3m[i] = __float2half_rn(v);
    }
    if (i < (size_t)(T_ * O3Q)) {
        int rp = (int)(i % O3Q), t = (int)(i / O3Q);
        int d = rp / 24, j = rp % 24;
        g_b3p[i] = (j < 23) ? b3[(size_t)t * O3 + d * 23 + j] : 0.f;
    }
}

__global__ void k_init(const float* __restrict__ z, const float* __restrict__ x) {
    int i = blockIdx.x * blockDim.x + threadIdx.x;
    if (i < B_ * XD) {
        int b = i / XD, j = i % XD;
        g_Acat[(size_t)b * KCAT + ZD + j] = __float2half_rn(x[i]);
    }
    if (i < B_ * ZD) {
        int b = i / ZD, d = i % ZD;
        g_Acat[(size_t)b * KCAT + d] = __float2half_rn(z[i]);
    }
    if (i < NDT * B_) g_ladp[i] = 0.f;
}

// ---------------- generic fp16 NT GEMM: C = A@W^T (+bias)(+aux)(relu) ----------------
constexpr int STAGE_BYTES = 32768;
constexpr int SMEM_BYTES  = 3 * STAGE_BYTES + 1024;

template <bool RELU, bool BIAS, bool AUX>
__global__ __launch_bounds__(128, 2)
void k_hg(const __half* __restrict__ A, int ldA, size_t zA,
          const __half* __restrict__ W, size_t zW,
          const float* __restrict__ bias, size_t zB,
          const __half* __restrict__ aux, size_t zX,
          __half* __restrict__ C, size_t zC,
          int K) {
    extern __shared__ char smraw[];
    const uint32_t base = (smem_u32(smraw) + 1023u) & ~1023u;

    const size_t zz = blockIdx.z;
    A += zz * zA;  W += zz * zW;  C += zz * zC;
    if (BIAS) bias += zz * zB;
    if (AUX)  aux  += zz * zX;

    const int tid  = threadIdx.x;
    const int warp = tid >> 5;
    const int lane = tid & 31;
    const int KC = K >> 6;

    const int trow = tid >> 3;
    const int c4   = tid & 7;
    const uint32_t sfix = (uint32_t)((c4 ^ (trow & 7)) * 16);
    const size_t KbA = (size_t)ldA * 2;
    const size_t KbW = (size_t)K * 2;
    const char* Ag = (const char*)A + (size_t)(blockIdx.y * 128 + trow) * KbA + c4 * 16;
    const char* Wg = (const char*)W + (size_t)(blockIdx.x * 128 + trow) * KbW + c4 * 16;

    auto issue = [&](int chunk) {
        const uint32_t stA = base + (uint32_t)(chunk % 3) * STAGE_BYTES;
        const uint32_t stB = stA + 16384;
        const size_t go = (size_t)chunk * 128;
#pragma unroll
        for (int i = 0; i < 8; i++) {
            uint32_t so = (uint32_t)(trow + 16 * i) * 128u + sfix;
            cpasync16(stA + so, Ag + (size_t)(16 * i) * KbA + go);
            cpasync16(stB + so, Wg + (size_t)(16 * i) * KbW + go);
        }
    };

    issue(0); cp_commit();
    if (KC > 1) issue(1);
    cp_commit();

    const int wm = (warp & 1) * 64;
    const int wn = (warp >> 1) * 64;
    const int lrow = lane & 15;
    const int lkh  = lane >> 4;

    float acc[4][8][4];
#pragma unroll
    for (int mf = 0; mf < 4; mf++)
#pragma unroll
        for (int nf = 0; nf < 8; nf++)
#pragma unroll
            for (int e = 0; e < 4; e++) acc[mf][nf][e] = 0.f;

    for (int i = 0; i < KC; i++) {
        cp_wait<1>();
        __syncthreads();
        if (i + 2 < KC) issue(i + 2);
        cp_commit();

        const uint32_t stA = base + (uint32_t)(i % 3) * STAGE_BYTES;
        const uint32_t stB = stA + 16384;
#pragma unroll
        for (int ks = 0; ks < 4; ks++) {
            uint32_t a[4][4], b[4][4];
#pragma unroll
            for (int mf = 0; mf < 4; mf++) {
                int row = wm + mf * 16 + lrow;
                uint32_t seg = (uint32_t)((2 * ks + lkh) ^ (row & 7));
                ldsm4(a[mf], stA + (uint32_t)row * 128u + seg * 16u);
            }
#pragma unroll
            for (int p = 0; p < 4; p++) {
                int row = wn + p * 16 + lrow;
                uint32_t seg = (uint32_t)((2 * ks + lkh) ^ (row & 7));
                ldsm4(b[p], stB + (uint32_t)row * 128u + seg * 16u);
            }
#pragma unroll
            for (int mf = 0; mf < 4; mf++)
#pragma unroll
                for (int p = 0; p < 4; p++) {
                    mma_f16(acc[mf][2 * p],     a[mf], b[p][0], b[p][2]);
                    mma_f16(acc[mf][2 * p + 1], a[mf], b[p][1], b[p][3]);
                }
        }
    }

    const int N = gridDim.x * 128;
    const int gm0 = blockIdx.y * 128 + wm + (lane >> 2);
    const int gn0 = blockIdx.x * 128 + wn + (lane & 3) * 2;
#pragma unroll
    for (int nf = 0; nf < 8; nf++) {
        const int cc = gn0 + nf * 8;
        float bv0 = 0.f, bv1 = 0.f;
        if (BIAS) { bv0 = bias[cc]; bv1 = bias[cc + 1]; }
#pragma unroll
        for (int mf = 0; mf < 4; mf++) {
            const size_t r0 = (size_t)(gm0 + mf * 16);
            float v0 = acc[mf][nf][0] + bv0;
            float v1 = acc[mf][nf][1] + bv1;
            float v2 = acc[mf][nf][2] + bv0;
            float v3 = acc[mf][nf][3] + bv1;
            if (AUX) {
                float2 x0 = __half22float2(*(const __half2*)(aux + r0 * N + cc));
                float2 x1 = __half22float2(*(const __half2*)(aux + (r0 + 8) * N + cc));
                v0 += x0.x; v1 += x0.y; v2 += x1.x; v3 += x1.y;
            }
            if (RELU) {
                v0 = fmaxf(v0, 0.f); v1 = fmaxf(v1, 0.f);
                v2 = fmaxf(v2, 0.f); v3 = fmaxf(v3, 0.f);
            }
            *(__half2*)(C + r0 * N + cc)       = __floats2half2_rn(v0, v1);
            *(__half2*)(C + (r0 + 8) * N + cc) = __floats2half2_rn(v2, v3);
        }
    }
}

// ---------------- fused GEMM3 + RQ-spline (16 tiles of 128x96 = 4 d's, 2 CTA/SM) ----------------
constexpr int G3_STAGE = 28672;
constexpr int G3_SMEM  = 3 * G3_STAGE + 1024;

__global__ __launch_bounds__(128, 2)
void k_g3spline(const __half* __restrict__ A, const __half* __restrict__ W,
                const float* __restrict__ bias) {
    extern __shared__ char smraw[];
    const uint32_t base = (smem_u32(smraw) + 1023u) & ~1023u;
    const uint32_t pad  = base - smem_u32(smraw);
    float* sp = (float*)(smraw + pad);

    const int tid  = threadIdx.x;
    const int warp = tid >> 5;
    const int lane = tid & 31;
    const int K = HID;

    const int Krun = c_k3b[blockIdx.x];
    const int KC = Krun >> 6;

    const int trow = tid >> 3;
    const int c4   = tid & 7;
    const uint32_t sfix = (uint32_t)((c4 ^ (trow & 7)) * 16);
    const size_t Kb = (size_t)K * 2;
    const char* Ag = (const char*)A + (size_t)(blockIdx.y * 128 + trow) * Kb + c4 * 16;
    const char* Wg = (const char*)W + (size_t)(blockIdx.x * 96 + trow) * Kb + c4 * 16;

    auto issue = [&](int chunk) {
        const uint32_t stA = base + (uint32_t)(chunk % 3) * G3_STAGE;
        const uint32_t stB = stA + 16384;
        const size_t go = (size_t)chunk * 128;
#pragma unroll
        for (int i = 0; i < 8; i++) {
            uint32_t so = (uint32_t)(trow + 16 * i) * 128u + sfix;
            cpasync16(stA + so, Ag + (size_t)(16 * i) * Kb + go);
            if (i < 6) cpasync16(stB + so, Wg + (size_t)(16 * i) * Kb + go);
        }
    };

    issue(0); cp_commit();
    if (KC > 1) issue(1);
    cp_commit();

    const int wm  = (warp & 1) * 64;
    const int wnl = (warp >> 1) * 48;
    const int lrow = lane & 15;
    const int lkh  = lane >> 4;

    float acc[4][6][4];
#pragma unroll
    for (int mf = 0; mf < 4; mf++)
#pragma unroll
        for (int nf = 0; nf < 6; nf++)
#pragma unroll
            for (int e = 0; e < 4; e++) acc[mf][nf][e] = 0.f;

    for (int i = 0; i < KC; i++) {
        cp_wait<1>();
        __syncthreads();
        if (i + 2 < KC) issue(i + 2);
        cp_commit();

        const uint32_t stA = base + (uint32_t)(i % 3) * G3_STAGE;
        const uint32_t stB = stA + 16384;
#pragma unroll
        for (int ks = 0; ks < 4; ks++) {
            uint32_t a[4][4], b[3][4];
#pragma unroll
            for (int mf = 0; mf < 4; mf++) {
                int row = wm + mf * 16 + lrow;
                uint32_t seg = (uint32_t)((2 * ks + lkh) ^ (row & 7));
                ldsm4(a[mf], stA + (uint32_t)row * 128u + seg * 16u);
            }
#pragma unroll
            for (int p = 0; p < 3; p++) {
                int row = wnl + p * 16 + lrow;
                uint32_t seg = (uint32_t)((2 * ks + lkh) ^ (row & 7));
                ldsm4(b[p], stB + (uint32_t)row * 128u + seg * 16u);
            }
#pragma unroll
            for (int mf = 0; mf < 4; mf++)
#pragma unroll
                for (int p = 0; p < 3; p++) {
                    mma_f16(acc[mf][2 * p],     a[mf], b[p][0], b[p][2]);
                    mma_f16(acc[mf][2 * p + 1], a[mf], b[p][1], b[p][3]);
                }
        }
    }

    cp_wait<0>();
    __syncthreads();

    {
        const int r0 = wm + (lane >> 2);
        const int c0 = wnl + (lane & 3) * 2;
        const int gb = blockIdx.x * 96;
#pragma unroll
        for (int nf = 0; nf < 6; nf++) {
            const int cc = c0 + nf * 8;
            const float bv0 = bias[gb + cc];
            const float bv1 = bias[gb + cc + 1];
#pragma unroll
            for (int mf = 0; mf < 4; mf++) {
                const int rr = r0 + mf * 16;
                sp[rr * 97 + cc]           = acc[mf][nf][0] + bv0;
                sp[rr * 97 + cc + 1]       = acc[mf][nf][1] + bv1;
                sp[(rr + 8) * 97 + cc]     = acc[mf][nf][2] + bv0;
                sp[(rr + 8) * 97 + cc + 1] = acc[mf][nf][3] + bv1;
            }
        }
    }
    __syncthreads();

    const int bglob = blockIdx.y * 128 + tid;
    const float ISH = 0.04419417382415922f;  // 1/sqrt(512)
    float ladsum = 0.f;
#pragma unroll 1
    for (int dl = 0; dl < 4; dl++) {
        const int d = blockIdx.x * 4 + dl;
        const float* pp = sp + tid * 97 + dl * 24;
        float z = __half2float(g_Acat[(size_t)bglob * KCAT + d]);

        float cumw[NB + 1], cumh[NB + 1];
        {
            float mx = pp[0];
#pragma unroll
            for (int i = 1; i < NB; i++) mx = fmaxf(mx, pp[i]);
            float e[NB], s = 0.f;
#pragma unroll
            for (int i = 0; i < NB; i++) { e[i] = fexp((pp[i] - mx) * ISH); s += e[i]; }
            float inv = __fdividef(1.f, s);
            const float fac = 1.f - NB * 0.001f;
            cumw[0] = -TAILF;
            float run = 0.f;
#pragma unroll
            for (int i = 0; i < NB; i++) {
                run += 0.001f + fac * e[i] * inv;
                cumw[i + 1] = -TAILF + 2.f * TAILF * run;
            }
            cumw[NB] = TAILF;
        }
        {
            float mx = pp[NB];
#pragma unroll
            for (int i = 1; i < NB; i++) mx = fmaxf(mx, pp[NB + i]);
            float e[NB], s = 0.f;
#pragma unroll
            for (int i = 0; i < NB; i++) { e[i] = fexp((pp[NB + i] - mx) * ISH); s += e[i]; }
            float inv = __fdividef(1.f, s);
            const float fac = 1.f - NB * 0.001f;
            cumh[0] = -TAILF;
            float run = 0.f;
#pragma unroll
            for (int i = 0; i < NB; i++) {
                run += 0.001f + fac * e[i] * inv;
                cumh[i + 1] = -TAILF + 2.f * TAILF * run;
            }
            cumh[NB] = TAILF;
        }

        float dv[NB + 1];
        dv[0] = 1.f; dv[NB] = 1.f;
#pragma unroll
        for (int k = 1; k < NB; k++) dv[k] = 0.001f + softplus_f(pp[2 * NB + k - 1]);

        float zin = fminf(fmaxf(z, -TAILF), TAILF);
        int idx = 0;
#pragma unroll
        for (int i = 1; i <= NB; i++) {
            float edge = cumw[i] + (i == NB ? 1e-6f : 0.f);
            idx += (zin >= edge) ? 1 : 0;
        }
        if (idx > NB - 1) idx = NB - 1;

        float in_cw = 0.f, in_w = 1.f, in_ch = 0.f, in_h = 1.f, d0 = 1.f, d1 = 1.f;
#pragma unroll
        for (int i = 0; i < NB; i++) {
            if (idx == i) {
                in_cw = cumw[i]; in_w = cumw[i + 1] - cumw[i];
                in_ch = cumh[i]; in_h = cumh[i + 1] - cumh[i];
                d0 = dv[i]; d1 = dv[i + 1];
            }
        }

        float rw = __fdividef(1.f, in_w);
        float delta = in_h * rw;
        float th  = (zin - in_cw) * rw;
        float th1 = th * (1.f - th);
        float num = in_h * (delta * th * th + d0 * th1);
        float den = delta + (d0 + d1 - 2.f * delta) * th1;
        float outv = in_ch + __fdividef(num, den);
        float omt = 1.f - th;
        float dnum = delta * delta * (d1 * th * th + 2.f * delta * th1 + d0 * omt * omt);
        float lad = __logf(dnum) - 2.f * __logf(den);

        bool inside = (z >= -TAILF) && (z <= TAILF);
        float newz = inside ? outv : z;
        ladsum += inside ? lad : 0.f;
        g_Acat[(size_t)bglob * KCAT + d] = __float2half_rn(newz);
    }
    g_ladp[blockIdx.x * B_ + bglob] += ladsum;
}

// ---------------- final log-prob ----------------
__global__ void k_final(float* __restrict__ out) {
    int warp = threadIdx.x >> 5;
    int b = blockIdx.x * 8 + warp;
    int lane = threadIdx.x & 31;
    float c1 = __half2float(g_Acat[(size_t)b * KCAT + lane]);
    float c2 = __half2float(g_Acat[(size_t)b * KCAT + 32 + lane]);
    float v = -0.5f * (c1 * c1 + c2 * c2);
    if (lane < NDT) v += g_ladp[lane * B_ + b];
#pragma unroll
    for (int off = 16; off; off >>= 1) v += __shfl_xor_sync(0xffffffffu, v, off);
    if (lane == 0) out[b] = v - 58.81206612510f;
}

// ---------------- launch ----------------
extern "C" void kernel_launch(void* const* d_in, const int* in_sizes, int n_in,
                              void* d_out, int out_size) {
    const float* z  = (const float*)d_in[0];
    const float* x  = (const float*)d_in[1];
    const float* W1 = (const float*)d_in[2];
    const float* b1 = (const float*)d_in[3];
    const float* Wc = (const float*)d_in[4];
    const float* bc = (const float*)d_in[5];
    const float* W2 = (const float*)d_in[6];
    const float* b2 = (const float*)d_in[7];
    const float* W3 = (const float*)d_in[8];
    const float* b3 = (const float*)d_in[9];
    float* out = (float*)d_out;

    void *pW2m, *pWcT, *pWxz, *pWcat2, *pBias2, *pW3m, *pB3p, *pAcat, *pH2;
    cudaGetSymbolAddress(&pW2m,   g_W2m);
    cudaGetSymbolAddress(&pWcT,   g_WcT);
    cudaGetSymbolAddress(&pWxz,   g_Wxz);
    cudaGetSymbolAddress(&pWcat2, g_Wcat2);
    cudaGetSymbolAddress(&pBias2, g_bias2);
    cudaGetSymbolAddress(&pW3m,   g_W3m);
    cudaGetSymbolAddress(&pB3p,   g_b3p);
    cudaGetSymbolAddress(&pAcat,  g_Acat);
    cudaGetSymbolAddress(&pH2,    g_h2);

    const __half* W2m  = (const __half*)pW2m;
    const __half* WcT  = (const __half*)pWcT;
    __half*       Wxz  = (__half*)pWxz;
    const __half* Wcat2= (const __half*)pWcat2;
    const float*  Bias2= (const float*)pBias2;
    const __half* W3m  = (const __half*)pW3m;
    const float*  B3p  = (const float*)pB3p;
    const __half* Acat = (const __half*)pAcat;
    __half*       H2   = (__half*)pH2;

    cudaFuncSetAttribute(k_hg<false, false, false>, cudaFuncAttributeMaxDynamicSharedMemorySize, SMEM_BYTES);
    cudaFuncSetAttribute(k_hg<true,  true,  false>, cudaFuncAttributeMaxDynamicSharedMemorySize, SMEM_BYTES);
    cudaFuncSetAttribute(k_g3spline, cudaFuncAttributeMaxDynamicSharedMemorySize, G3_SMEM);

    // ---- prep (parallelized) ----
    k_prep_w2<<<(T_ * HID * HID + 255) / 256, 256>>>(W2);
    k_prep_wcT<<<(T_ * XD * HID + 255) / 256, 256>>>(Wc);
    k_prep_wz<<<T_ * HID, 256>>>(W1, W2);
    k_prep_bias2<<<(T_ * HID * 32 + 255) / 256, 256>>>(W2, b1, bc, b2);
    {
        size_t tot = (size_t)T_ * O3Q * HID;
        k_prep_w3<<<(int)((tot + 255) / 256), 256>>>(W3, b3);
    }
    k_init<<<(B_ * XD + 255) / 256, 256>>>(z, x);

    // Wxz = W2m @ WcT^T (dense, ld = 256 = gridDim.x*128) : M=512, N=256, K=512, batched t
    {
        dim3 g(2, 4, 8);
        k_hg<false, false, false><<<g, 128, SMEM_BYTES>>>(
            W2m, HID, (size_t)HID * HID,
            WcT, (size_t)XD * HID,
            nullptr, 0, nullptr, 0,
            Wxz, (size_t)HID * XD, HID);
    }
    // pack Wxz into Wcat2 cols [64,320)
    k_pack<<<(T_ * HID * XD + 255) / 256, 256>>>();

    dim3 g2(4, 256, 1);
    dim3 g3(NDT, 256);   // 16 tiles x 256 b-tiles — covers all 64 z-dims
    for (int t = 0; t < T_; t++) {
        // H2 = relu(Acat @ Wcat2_t^T + bias2_t)  : K=320
        k_hg<true, true, false><<<g2, 128, SMEM_BYTES>>>(
            Acat, KCAT, 0,
            Wcat2 + (size_t)t * HID * KCAT, 0,
            Bias2 + t * HID, 0,
            nullptr, 0,
            H2, 0, KCAT);
        k_g3spline<<<g3, 128, G3_SMEM>>>(H2, W3m + (size_t)t * O3Q * HID,
                                         B3p + (size_t)t * O3Q);
    }
    k_final<<<B_ / 8, 256>>>(out);
}